// round 3
// baseline (speedup 1.0000x reference)
#include <cuda_runtime.h>
#include <math.h>

#define HIDDEN  256
#define N_PROT  12288
#define N_MOL   6144
#define N_BATCH 32
#define TQ      16                      // prot rows per attn block
#define MSEG    512                     // max mol rows per batch (mean 192, sd 13.6 -> 23 sigma)
#define MAXTILES (N_PROT / TQ + N_BATCH)

// Scratch (device globals: allocation-free per harness rules)
__device__ float g_Q[N_PROT * HIDDEN];
__device__ float g_K[N_MOL * HIDDEN];
__device__ float g_V[N_MOL * HIDDEN];
__device__ int   g_ss[N_BATCH];
__device__ int   g_se[N_BATCH];
__device__ int   g_trow[MAXTILES];
__device__ int   g_tn[MAXTILES];
__device__ int   g_tb[MAXTILES];
__device__ int   g_ntiles;

// ---------------------------------------------------------------------------
// Setup: per-batch mol segment bounds + prot row tiles (histogram + prefix).
// ---------------------------------------------------------------------------
__global__ __launch_bounds__(256) void setup_kernel(
    const int* __restrict__ prot_batch, const int* __restrict__ mol_batch)
{
    __shared__ int mc[N_BATCH], pc[N_BATCH];
    const int tid = threadIdx.x;
    if (tid < N_BATCH) { mc[tid] = 0; pc[tid] = 0; }
    __syncthreads();
    for (int i = tid; i < N_MOL;  i += 256) atomicAdd(&mc[mol_batch[i]], 1);
    for (int i = tid; i < N_PROT; i += 256) atomicAdd(&pc[prot_batch[i]], 1);
    __syncthreads();
    if (tid == 0) {
        int ms = 0, ps = 0, t = 0;
        for (int b = 0; b < N_BATCH; b++) {
            g_ss[b] = ms; g_se[b] = ms + mc[b]; ms += mc[b];
            const int np = pc[b];
            for (int k = 0; k < np; k += TQ) {
                g_trow[t] = ps + k;
                g_tn[t]   = (np - k < TQ) ? (np - k) : TQ;
                g_tb[t]   = b;
                t++;
            }
            ps += np;
        }
        g_ntiles = t;
    }
}

// ---------------------------------------------------------------------------
// Projection GEMM: C[M,256] = X[M,256] @ W[256,256]^T + bias
// 64x64 tile, BK=16, 256 threads, 4x4 per thread, LDS.128 mainloop.
// ---------------------------------------------------------------------------
__global__ __launch_bounds__(256) void proj_kernel(
    const float* __restrict__ X, const float* __restrict__ W,
    const float* __restrict__ bias, int which)
{
    constexpr int BM = 64, BN = 64, BK = 16;
    __shared__ __align__(16) float Xs[BK][BM + 4];
    __shared__ __align__(16) float Ws[BK][BN + 4];

    float* __restrict__ C = (which == 0) ? g_Q : (which == 1) ? g_K : g_V;

    const int tx = threadIdx.x & 15;
    const int ty = threadIdx.x >> 4;
    const int row0 = blockIdx.x * BM;
    const int col0 = blockIdx.y * BN;

    const int lk = threadIdx.x & (BK - 1);
    const int lr = threadIdx.x / BK;

    float acc[4][4] = {};

    for (int k0 = 0; k0 < HIDDEN; k0 += BK) {
        #pragma unroll
        for (int r = 0; r < BM; r += 16) {
            Xs[lk][lr + r] = X[(size_t)(row0 + lr + r) * HIDDEN + k0 + lk];
            Ws[lk][lr + r] = W[(size_t)(col0 + lr + r) * HIDDEN + k0 + lk];
        }
        __syncthreads();
        #pragma unroll
        for (int kk = 0; kk < BK; kk++) {
            const float4 a = *(const float4*)&Xs[kk][ty * 4];
            const float4 b = *(const float4*)&Ws[kk][tx * 4];
            const float av[4] = {a.x, a.y, a.z, a.w};
            const float bv[4] = {b.x, b.y, b.z, b.w};
            #pragma unroll
            for (int i = 0; i < 4; i++)
                #pragma unroll
                for (int j = 0; j < 4; j++)
                    acc[i][j] = fmaf(av[i], bv[j], acc[i][j]);
        }
        __syncthreads();
    }

    #pragma unroll
    for (int i = 0; i < 4; i++) {
        #pragma unroll
        for (int j = 0; j < 4; j++) {
            const int c = col0 + tx * 4 + j;
            C[(size_t)(row0 + ty * 4 + i) * HIDDEN + c] = acc[i][j] + bias[c];
        }
    }
}

// ---------------------------------------------------------------------------
// Attention: one block (256 threads) per tile of TQ=16 prot rows (same batch).
// Each warp owns 2 Q rows; for EVERY key the two half-warps compute the two
// rows' full 256-dot (16 floats/lane, xor-reduce within half-warp).
// Both halves read identical K addresses -> coalesced single transactions.
// ---------------------------------------------------------------------------
__global__ __launch_bounds__(256) void attn_kernel(
    float* __restrict__ out, float* __restrict__ attn)
{
    const int t = blockIdx.x;
    if (t >= g_ntiles) return;

    const int row0 = g_trow[t];
    const int nr   = g_tn[t];
    const int b    = g_tb[t];
    const int s    = g_ss[b];
    int m = g_se[b] - s;
    if (m > MSEG) m = MSEG;          // unreachable; memory safety
    const int e_eff = s + m;

    __shared__ __align__(16) float sc[TQ * MSEG];

    const int tid  = threadIdx.x;
    const int warp = tid >> 5;
    const int lane = tid & 31;

    if (m > 0) {
        // Half-warp h (lane>=16 -> h=1) handles row r0+h. hl = lane within half.
        const int h  = lane >> 4;
        const int hl = lane & 15;
        const int r0 = warp * 2;
        const int rr = r0 + h;
        const int qr = row0 + ((rr < nr) ? rr : nr - 1);

        // 16 floats of Q per lane (4 float4s, strided by 16 lanes)
        const float4* Q4 = (const float4*)g_Q + (size_t)qr * 64;
        const float4 q0 = Q4[hl];
        const float4 q1 = Q4[hl + 16];
        const float4 q2 = Q4[hl + 32];
        const float4 q3 = Q4[hl + 48];

        for (int j = 0; j < m; j++) {
            const float4* K4 = (const float4*)g_K + (size_t)(s + j) * 64;
            const float4 k0 = K4[hl];
            const float4 k1 = K4[hl + 16];
            const float4 k2 = K4[hl + 32];
            const float4 k3 = K4[hl + 48];
            float d = q0.x*k0.x + q0.y*k0.y + q0.z*k0.z + q0.w*k0.w
                    + q1.x*k1.x + q1.y*k1.y + q1.z*k1.z + q1.w*k1.w
                    + q2.x*k2.x + q2.y*k2.y + q2.z*k2.z + q2.w*k2.w
                    + q3.x*k3.x + q3.y*k3.y + q3.z*k3.z + q3.w*k3.w;
            #pragma unroll
            for (int off = 8; off; off >>= 1)
                d += __shfl_xor_sync(0xffffffffu, d, off);
            if (hl == 0) sc[rr * MSEG + j] = d * 0.0625f;   // 1/sqrt(256)
        }
        __syncthreads();

        // Softmax: warp w normalizes rows 2w, 2w+1 (warp-level reductions).
        #pragma unroll
        for (int rr2 = 0; rr2 < 2; rr2++) {
            float* row = sc + (warp * 2 + rr2) * MSEG;
            float mx = -INFINITY;
            for (int j = lane; j < m; j += 32) mx = fmaxf(mx, row[j]);
            #pragma unroll
            for (int off = 16; off; off >>= 1)
                mx = fmaxf(mx, __shfl_xor_sync(0xffffffffu, mx, off));
            float sum = 0.f;
            for (int j = lane; j < m; j += 32) {
                const float v = __expf(row[j] - mx);
                row[j] = v;
                sum += v;
            }
            #pragma unroll
            for (int off = 16; off; off >>= 1)
                sum += __shfl_xor_sync(0xffffffffu, sum, off);
            const float inv = 1.f / sum;
            for (int j = lane; j < m; j += 32) row[j] *= inv;
        }
        __syncthreads();
    }

    // Write full attn rows (zeros outside [s, e_eff)), float4 coalesced.
    for (int r = 0; r < nr; r++) {
        float4* arow = (float4*)(attn + (size_t)(row0 + r) * N_MOL);
        const float* row = sc + r * MSEG;
        for (int c4 = tid; c4 < N_MOL / 4; c4 += 256) {
            const int c = c4 * 4;
            float4 v = {0.f, 0.f, 0.f, 0.f};
            if (m > 0 && c + 3 >= s && c < e_eff) {
                if (c + 0 >= s && c + 0 < e_eff) v.x = row[c + 0 - s];
                if (c + 1 >= s && c + 1 < e_eff) v.y = row[c + 1 - s];
                if (c + 2 >= s && c + 2 < e_eff) v.z = row[c + 2 - s];
                if (c + 3 >= s && c + 3 < e_eff) v.w = row[c + 3 - s];
            }
            arow[c4] = v;
        }
    }

    // out[row0+r][tid] = sum_j p[r][j] * V[s+j][tid]; 16 register accumulators.
    float acc[TQ];
    #pragma unroll
    for (int r = 0; r < TQ; r++) acc[r] = 0.f;

    int j = 0;
    for (; j + 3 < m; j += 4) {
        const float v0 = g_V[(size_t)(s + j + 0) * HIDDEN + tid];
        const float v1 = g_V[(size_t)(s + j + 1) * HIDDEN + tid];
        const float v2 = g_V[(size_t)(s + j + 2) * HIDDEN + tid];
        const float v3 = g_V[(size_t)(s + j + 3) * HIDDEN + tid];
        #pragma unroll
        for (int r = 0; r < TQ; r++) {
            const float4 p = *(const float4*)&sc[r * MSEG + j];
            float a = acc[r];
            a = fmaf(p.x, v0, a);
            a = fmaf(p.y, v1, a);
            a = fmaf(p.z, v2, a);
            a = fmaf(p.w, v3, a);
            acc[r] = a;
        }
    }
    for (; j < m; j++) {
        const float v0 = g_V[(size_t)(s + j) * HIDDEN + tid];
        #pragma unroll
        for (int r = 0; r < TQ; r++)
            acc[r] = fmaf(sc[r * MSEG + j], v0, acc[r]);
    }

    #pragma unroll
    for (int r = 0; r < TQ; r++)
        if (r < nr) out[(size_t)(row0 + r) * HIDDEN + tid] = acc[r];
}

// ---------------------------------------------------------------------------
extern "C" void kernel_launch(void* const* d_in, const int* in_sizes, int n_in,
                              void* d_out, int out_size)
{
    const float* prot_embed = (const float*)d_in[0];
    const float* mol_embed  = (const float*)d_in[1];
    const int*   prot_batch = (const int*)d_in[2];
    const int*   mol_batch  = (const int*)d_in[3];
    const float* Wq = (const float*)d_in[4];
    const float* bq = (const float*)d_in[5];
    const float* Wk = (const float*)d_in[6];
    const float* bk = (const float*)d_in[7];
    const float* Wv = (const float*)d_in[8];
    const float* bv = (const float*)d_in[9];

    float* out  = (float*)d_out;                              // [N_PROT, HIDDEN]
    float* attn = (float*)d_out + (size_t)N_PROT * HIDDEN;    // [N_PROT, N_MOL]

    setup_kernel<<<1, 256>>>(prot_batch, mol_batch);

    {
        dim3 gq(N_PROT / 64, HIDDEN / 64);
        dim3 gm(N_MOL / 64, HIDDEN / 64);
        proj_kernel<<<gq, 256>>>(prot_embed, Wq, bq, 0);
        proj_kernel<<<gm, 256>>>(mol_embed,  Wk, bk, 1);
        proj_kernel<<<gm, 256>>>(mol_embed,  Wv, bv, 2);
    }

    attn_kernel<<<MAXTILES, 256>>>(out, attn);
}

// round 4
// speedup vs baseline: 1.4249x; 1.4249x over previous
#include <cuda_runtime.h>
#include <math.h>

#define HIDDEN  256
#define N_PROT  12288
#define N_MOL   6144
#define N_BATCH 32
#define TQ      16                      // prot rows per attn block
#define MSEG    512                     // max mol rows per batch (mean 192, sd 13.6 -> 23 sigma)
#define CKEYS   32                      // K rows staged per chunk (32 KB smem)
#define MAXTILES (N_PROT / TQ + N_BATCH)

// Scratch (device globals: allocation-free per harness rules)
__device__ float g_Q[N_PROT * HIDDEN];
__device__ float g_K[N_MOL * HIDDEN];
__device__ float g_V[N_MOL * HIDDEN];
__device__ int   g_ss[N_BATCH];
__device__ int   g_se[N_BATCH];
__device__ int   g_trow[MAXTILES];
__device__ int   g_tn[MAXTILES];
__device__ int   g_tb[MAXTILES];
__device__ int   g_ntiles;

// ---------------------------------------------------------------------------
// Setup: boundary scan on the SORTED batch arrays (atomic-free) + tile build.
// ---------------------------------------------------------------------------
__global__ __launch_bounds__(256) void setup_kernel(
    const int* __restrict__ prot_batch, const int* __restrict__ mol_batch)
{
    __shared__ int ms[N_BATCH + 1], ps[N_BATCH + 1];
    const int tid = threadIdx.x;

    for (int i = tid; i < N_MOL; i += 256) {
        const int v   = mol_batch[i];
        const int nxt = (i + 1 < N_MOL) ? mol_batch[i + 1] : N_BATCH;
        if (i == 0) for (int bb = 0; bb <= v; bb++) ms[bb] = 0;
        for (int bb = v + 1; bb <= nxt; bb++) ms[bb] = i + 1;
    }
    for (int i = tid; i < N_PROT; i += 256) {
        const int v   = prot_batch[i];
        const int nxt = (i + 1 < N_PROT) ? prot_batch[i + 1] : N_BATCH;
        if (i == 0) for (int bb = 0; bb <= v; bb++) ps[bb] = 0;
        for (int bb = v + 1; bb <= nxt; bb++) ps[bb] = i + 1;
    }
    __syncthreads();

    if (tid < N_BATCH) { g_ss[tid] = ms[tid]; g_se[tid] = ms[tid + 1]; }

    if (tid < 32) {   // warp 0: per-batch tile counts + exclusive warp scan
        const int p0 = ps[tid];
        const int np = ps[tid + 1] - p0;
        const int nt = (np + TQ - 1) / TQ;
        int off = nt;
        #pragma unroll
        for (int d = 1; d < 32; d <<= 1) {
            const int n = __shfl_up_sync(0xffffffffu, off, d);
            if (tid >= d) off += n;
        }
        const int base = off - nt;   // exclusive prefix
        for (int k = 0; k < nt; k++) {
            g_trow[base + k] = p0 + k * TQ;
            g_tn[base + k]   = (np - k * TQ < TQ) ? (np - k * TQ) : TQ;
            g_tb[base + k]   = tid;
        }
        if (tid == 31) g_ntiles = off;
    }
}

// ---------------------------------------------------------------------------
// Fused projection GEMMs (Q, K, V in ONE launch, flat block decode):
// C[M,256] = X[M,256] @ W[256,256]^T + bias
// 64x64 tile, BK=16, 256 threads, 4x4 microtile, LDS.128 mainloop.
// Block ranges: [0,768) -> Q (192 row-blocks), [768,1152) -> K, [1152,1536) -> V
// ---------------------------------------------------------------------------
__global__ __launch_bounds__(256) void proj_kernel(
    const float* __restrict__ prot_embed, const float* __restrict__ mol_embed,
    const float* __restrict__ Wq, const float* __restrict__ bq,
    const float* __restrict__ Wk, const float* __restrict__ bk,
    const float* __restrict__ Wv, const float* __restrict__ bv)
{
    constexpr int BM = 64, BN = 64, BK = 16;
    __shared__ __align__(16) float Xs[BK][BM + 4];
    __shared__ __align__(16) float Ws[BK][BN + 4];

    const int bid = blockIdx.x;
    const float* X; const float* W; const float* bias; float* C;
    int local;
    if (bid < 768)       { local = bid;        X = prot_embed; W = Wq; bias = bq; C = g_Q; }
    else if (bid < 1152) { local = bid - 768;  X = mol_embed;  W = Wk; bias = bk; C = g_K; }
    else                 { local = bid - 1152; X = mol_embed;  W = Wv; bias = bv; C = g_V; }
    const int row0 = (local >> 2) * BM;
    const int col0 = (local & 3) * BN;

    const int tx = threadIdx.x & 15;
    const int ty = threadIdx.x >> 4;
    const int lk = threadIdx.x & (BK - 1);
    const int lr = threadIdx.x / BK;

    float acc[4][4] = {};

    for (int k0 = 0; k0 < HIDDEN; k0 += BK) {
        #pragma unroll
        for (int r = 0; r < BM; r += 16) {
            Xs[lk][lr + r] = X[(size_t)(row0 + lr + r) * HIDDEN + k0 + lk];
            Ws[lk][lr + r] = W[(size_t)(col0 + lr + r) * HIDDEN + k0 + lk];
        }
        __syncthreads();
        #pragma unroll
        for (int kk = 0; kk < BK; kk++) {
            const float4 a = *(const float4*)&Xs[kk][ty * 4];
            const float4 b = *(const float4*)&Ws[kk][tx * 4];
            const float av[4] = {a.x, a.y, a.z, a.w};
            const float bv4[4] = {b.x, b.y, b.z, b.w};
            #pragma unroll
            for (int i = 0; i < 4; i++)
                #pragma unroll
                for (int j = 0; j < 4; j++)
                    acc[i][j] = fmaf(av[i], bv4[j], acc[i][j]);
        }
        __syncthreads();
    }

    #pragma unroll
    for (int i = 0; i < 4; i++) {
        #pragma unroll
        for (int j = 0; j < 4; j++) {
            const int c = col0 + tx * 4 + j;
            C[(size_t)(row0 + ty * 4 + i) * HIDDEN + c] = acc[i][j] + bias[c];
        }
    }
}

// ---------------------------------------------------------------------------
// Attention: one block (256 threads) per tile of TQ=16 prot rows (same batch).
// K is staged into smem in 32-key chunks ONCE per block (8x less L2 traffic
// than the per-warp global reads of R3). Each warp owns 2 Q rows; the two
// half-warps compute the two rows' dot against the smem key (broadcast reads,
// conflict-free), then 4-level xor reduce within the half-warp.
// ---------------------------------------------------------------------------
__global__ __launch_bounds__(256) void attn_kernel(
    float* __restrict__ out, float* __restrict__ attn)
{
    const int t = blockIdx.x;
    if (t >= g_ntiles) return;

    const int row0 = g_trow[t];
    const int nr   = g_tn[t];
    const int b    = g_tb[t];
    const int s    = g_ss[b];
    int m = g_se[b] - s;
    if (m > MSEG) m = MSEG;          // unreachable; memory safety
    const int e_eff = s + m;

    __shared__ __align__(16) float sc[TQ * MSEG];        // 32 KB
    __shared__ __align__(16) float Ks[CKEYS * HIDDEN];   // 32 KB

    const int tid  = threadIdx.x;
    const int warp = tid >> 5;
    const int lane = tid & 31;

    if (m > 0) {
        // Half-warp h handles row warp*2+h; hl = lane within half.
        const int h  = lane >> 4;
        const int hl = lane & 15;
        const int rr = warp * 2 + h;
        const int qr = row0 + ((rr < nr) ? rr : nr - 1);

        const float4* Q4 = (const float4*)g_Q + (size_t)qr * 64;
        const float4 q0 = Q4[hl];
        const float4 q1 = Q4[hl + 16];
        const float4 q2 = Q4[hl + 32];
        const float4 q3 = Q4[hl + 48];

        float4* Ks4 = (float4*)Ks;

        for (int c0 = 0; c0 < m; c0 += CKEYS) {
            const int cn = (m - c0 < CKEYS) ? (m - c0) : CKEYS;
            __syncthreads();   // previous chunk's reads complete
            // stage cn keys: contiguous float4 copy (coalesced)
            const float4* Kg = (const float4*)g_K + (size_t)(s + c0) * 64;
            for (int idx = tid; idx < cn * 64; idx += 256)
                Ks4[idx] = Kg[idx];
            __syncthreads();

            for (int j = 0; j < cn; j++) {
                const float4* Kr = Ks4 + j * 64;
                const float4 k0 = Kr[hl];
                const float4 k1 = Kr[hl + 16];
                const float4 k2 = Kr[hl + 32];
                const float4 k3 = Kr[hl + 48];
                float d = q0.x*k0.x + q0.y*k0.y + q0.z*k0.z + q0.w*k0.w
                        + q1.x*k1.x + q1.y*k1.y + q1.z*k1.z + q1.w*k1.w
                        + q2.x*k2.x + q2.y*k2.y + q2.z*k2.z + q2.w*k2.w
                        + q3.x*k3.x + q3.y*k3.y + q3.z*k3.z + q3.w*k3.w;
                #pragma unroll
                for (int off = 8; off; off >>= 1)
                    d += __shfl_xor_sync(0xffffffffu, d, off);
                if (hl == 0) sc[rr * MSEG + c0 + j] = d * 0.0625f;  // 1/sqrt(256)
            }
        }
        __syncthreads();

        // Softmax: warp w normalizes rows 2w, 2w+1 (warp-level reductions).
        #pragma unroll
        for (int rr2 = 0; rr2 < 2; rr2++) {
            float* row = sc + (warp * 2 + rr2) * MSEG;
            float mx = -INFINITY;
            for (int j = lane; j < m; j += 32) mx = fmaxf(mx, row[j]);
            #pragma unroll
            for (int off = 16; off; off >>= 1)
                mx = fmaxf(mx, __shfl_xor_sync(0xffffffffu, mx, off));
            float sum = 0.f;
            for (int j = lane; j < m; j += 32) {
                const float v = __expf(row[j] - mx);
                row[j] = v;
                sum += v;
            }
            #pragma unroll
            for (int off = 16; off; off >>= 1)
                sum += __shfl_xor_sync(0xffffffffu, sum, off);
            const float inv = 1.f / sum;
            for (int j = lane; j < m; j += 32) row[j] *= inv;
        }
        __syncthreads();
    }

    // Write full attn rows (zeros outside [s, e_eff)), float4 coalesced.
    for (int r = 0; r < nr; r++) {
        float4* arow = (float4*)(attn + (size_t)(row0 + r) * N_MOL);
        const float* row = sc + r * MSEG;
        for (int c4 = tid; c4 < N_MOL / 4; c4 += 256) {
            const int c = c4 * 4;
            float4 v = {0.f, 0.f, 0.f, 0.f};
            if (m > 0 && c + 3 >= s && c < e_eff) {
                if (c + 0 >= s && c + 0 < e_eff) v.x = row[c + 0 - s];
                if (c + 1 >= s && c + 1 < e_eff) v.y = row[c + 1 - s];
                if (c + 2 >= s && c + 2 < e_eff) v.z = row[c + 2 - s];
                if (c + 3 >= s && c + 3 < e_eff) v.w = row[c + 3 - s];
            }
            arow[c4] = v;
        }
    }

    // out[row0+r][tid] = sum_j p[r][j] * V[s+j][tid]; 16 register accumulators.
    float acc[TQ];
    #pragma unroll
    for (int r = 0; r < TQ; r++) acc[r] = 0.f;

    int j = 0;
    for (; j + 3 < m; j += 4) {
        const float v0 = g_V[(size_t)(s + j + 0) * HIDDEN + tid];
        const float v1 = g_V[(size_t)(s + j + 1) * HIDDEN + tid];
        const float v2 = g_V[(size_t)(s + j + 2) * HIDDEN + tid];
        const float v3 = g_V[(size_t)(s + j + 3) * HIDDEN + tid];
        #pragma unroll
        for (int r = 0; r < TQ; r++) {
            const float4 p = *(const float4*)&sc[r * MSEG + j];
            float a = acc[r];
            a = fmaf(p.x, v0, a);
            a = fmaf(p.y, v1, a);
            a = fmaf(p.z, v2, a);
            a = fmaf(p.w, v3, a);
            acc[r] = a;
        }
    }
    for (; j < m; j++) {
        const float v0 = g_V[(size_t)(s + j) * HIDDEN + tid];
        #pragma unroll
        for (int r = 0; r < TQ; r++)
            acc[r] = fmaf(sc[r * MSEG + j], v0, acc[r]);
    }

    #pragma unroll
    for (int r = 0; r < TQ; r++)
        if (r < nr) out[(size_t)(row0 + r) * HIDDEN + tid] = acc[r];
}

// ---------------------------------------------------------------------------
extern "C" void kernel_launch(void* const* d_in, const int* in_sizes, int n_in,
                              void* d_out, int out_size)
{
    const float* prot_embed = (const float*)d_in[0];
    const float* mol_embed  = (const float*)d_in[1];
    const int*   prot_batch = (const int*)d_in[2];
    const int*   mol_batch  = (const int*)d_in[3];
    const float* Wq = (const float*)d_in[4];
    const float* bq = (const float*)d_in[5];
    const float* Wk = (const float*)d_in[6];
    const float* bk = (const float*)d_in[7];
    const float* Wv = (const float*)d_in[8];
    const float* bv = (const float*)d_in[9];

    float* out  = (float*)d_out;                              // [N_PROT, HIDDEN]
    float* attn = (float*)d_out + (size_t)N_PROT * HIDDEN;    // [N_PROT, N_MOL]

    setup_kernel<<<1, 256>>>(prot_batch, mol_batch);
    proj_kernel<<<1536, 256>>>(prot_embed, mol_embed, Wq, bq, Wk, bk, Wv, bv);
    attn_kernel<<<MAXTILES, 256>>>(out, attn);
}

// round 5
// speedup vs baseline: 1.5635x; 1.0972x over previous
#include <cuda_runtime.h>
#include <math.h>

#define HIDDEN  256
#define N_PROT  12288
#define N_MOL   6144
#define N_BATCH 32
#define TQ      16                      // prot rows per attn block
#define MSEG    512                     // max mol rows per batch (mean 192, sd 13.6 -> 23 sigma)
#define CKEYS   32                      // K rows staged per chunk (32 KB smem)
#define MAXTILES (N_PROT / TQ + N_BATCH)

#define NPROJ   1536                    // proj blocks (Q:768, K:384, V:384)
#define NZERO   4608                    // zero-fill blocks for attn matrix
#define ATTN_F4 ((size_t)N_PROT * N_MOL / 4)

// Scratch (device globals: allocation-free per harness rules)
__device__ float g_Q[N_PROT * HIDDEN];
__device__ float g_K[N_MOL * HIDDEN];
__device__ float g_V[N_MOL * HIDDEN];
__device__ int   g_ms[N_BATCH + 1];     // mol  segment boundaries
__device__ int   g_ps[N_BATCH + 1];     // prot segment boundaries
__device__ int   g_ss[N_BATCH];
__device__ int   g_se[N_BATCH];
__device__ int   g_trow[MAXTILES];
__device__ int   g_tn[MAXTILES];
__device__ int   g_tb[MAXTILES];
__device__ int   g_ntiles;

// ---------------------------------------------------------------------------
// Parallel boundary detection on the SORTED batch arrays.
// g_ms[b] = first mol index with batch >= b (g_ms[32] = N_MOL). Same for g_ps.
// ---------------------------------------------------------------------------
__global__ __launch_bounds__(256) void bounds_kernel(
    const int* __restrict__ prot_batch, const int* __restrict__ mol_batch)
{
    const int i = blockIdx.x * 256 + threadIdx.x;
    if (i < N_MOL) {
        const int v = mol_batch[i];
        const int p = (i > 0) ? mol_batch[i - 1] : -1;
        for (int bb = p + 1; bb <= v; bb++) g_ms[bb] = i;
        if (i == N_MOL - 1)
            for (int bb = v + 1; bb <= N_BATCH; bb++) g_ms[bb] = N_MOL;
    }
    if (i < N_PROT) {
        const int v = prot_batch[i];
        const int p = (i > 0) ? prot_batch[i - 1] : -1;
        for (int bb = p + 1; bb <= v; bb++) g_ps[bb] = i;
        if (i == N_PROT - 1)
            for (int bb = v + 1; bb <= N_BATCH; bb++) g_ps[bb] = N_PROT;
    }
}

// ---------------------------------------------------------------------------
// Tile build: 1 warp. Reads 33+33 ints, warp-scan, writes tile table.
// ---------------------------------------------------------------------------
__global__ void tiles_kernel()
{
    const int tid = threadIdx.x;
    if (tid >= 32) return;
    g_ss[tid] = g_ms[tid];
    g_se[tid] = g_ms[tid + 1];

    const int p0 = g_ps[tid];
    const int np = g_ps[tid + 1] - p0;
    const int nt = (np + TQ - 1) / TQ;
    int off = nt;
    #pragma unroll
    for (int d = 1; d < 32; d <<= 1) {
        const int n = __shfl_up_sync(0xffffffffu, off, d);
        if (tid >= d) off += n;
    }
    const int base = off - nt;   // exclusive prefix
    for (int k = 0; k < nt; k++) {
        g_trow[base + k] = p0 + k * TQ;
        g_tn[base + k]   = (np - k * TQ < TQ) ? (np - k * TQ) : TQ;
        g_tb[base + k]   = tid;
    }
    if (tid == 31) g_ntiles = off;
}

// ---------------------------------------------------------------------------
// Fused: projection GEMMs (Q,K,V) + attn-matrix zero-fill in ONE launch.
// Role by bid%4: (bid&3)==0 -> GEMM block (1536 of them), else zero-fill
// (4608). Interleaving lets DRAM-write blocks overlap FFMA-bound GEMM blocks.
// GEMM: C[M,256] = X[M,256] @ W[256,256]^T + bias (64x64 tile, BK=16).
// ---------------------------------------------------------------------------
__global__ __launch_bounds__(256) void proj_zero_kernel(
    const float* __restrict__ prot_embed, const float* __restrict__ mol_embed,
    const float* __restrict__ Wq, const float* __restrict__ bq,
    const float* __restrict__ Wk, const float* __restrict__ bk,
    const float* __restrict__ Wv, const float* __restrict__ bv,
    float* __restrict__ attn)
{
    const int bid = blockIdx.x;

    if (bid & 3) {
        // ---- zero-fill role: grid-stride float4 stores over 302 MB ----
        const size_t zidx = (size_t)(bid - (bid >> 2) - 1);
        float4* a4 = (float4*)attn;
        const float4 z = {0.f, 0.f, 0.f, 0.f};
        const size_t stride = (size_t)NZERO * 256;
        for (size_t i = zidx * 256 + threadIdx.x; i < ATTN_F4; i += stride)
            a4[i] = z;
        return;
    }

    // ---- GEMM role ----
    constexpr int BM = 64, BN = 64, BK = 16;
    __shared__ __align__(16) float Xs[BK][BM + 4];
    __shared__ __align__(16) float Ws[BK][BN + 4];

    const int gb = bid >> 2;                  // 0..1535
    const float* X; const float* W; const float* bias; float* C;
    int local;
    if (gb < 768)       { local = gb;        X = prot_embed; W = Wq; bias = bq; C = g_Q; }
    else if (gb < 1152) { local = gb - 768;  X = mol_embed;  W = Wk; bias = bk; C = g_K; }
    else                { local = gb - 1152; X = mol_embed;  W = Wv; bias = bv; C = g_V; }
    const int row0 = (local >> 2) * BM;
    const int col0 = (local & 3) * BN;

    const int tx = threadIdx.x & 15;
    const int ty = threadIdx.x >> 4;
    const int lk = threadIdx.x & (BK - 1);
    const int lr = threadIdx.x / BK;

    float acc[4][4] = {};

    for (int k0 = 0; k0 < HIDDEN; k0 += BK) {
        #pragma unroll
        for (int r = 0; r < BM; r += 16) {
            Xs[lk][lr + r] = X[(size_t)(row0 + lr + r) * HIDDEN + k0 + lk];
            Ws[lk][lr + r] = W[(size_t)(col0 + lr + r) * HIDDEN + k0 + lk];
        }
        __syncthreads();
        #pragma unroll
        for (int kk = 0; kk < BK; kk++) {
            const float4 a = *(const float4*)&Xs[kk][ty * 4];
            const float4 b = *(const float4*)&Ws[kk][tx * 4];
            const float av[4] = {a.x, a.y, a.z, a.w};
            const float bv4[4] = {b.x, b.y, b.z, b.w};
            #pragma unroll
            for (int i = 0; i < 4; i++)
                #pragma unroll
                for (int j = 0; j < 4; j++)
                    acc[i][j] = fmaf(av[i], bv4[j], acc[i][j]);
        }
        __syncthreads();
    }

    #pragma unroll
    for (int i = 0; i < 4; i++) {
        #pragma unroll
        for (int j = 0; j < 4; j++) {
            const int c = col0 + tx * 4 + j;
            C[(size_t)(row0 + ty * 4 + i) * HIDDEN + c] = acc[i][j] + bias[c];
        }
    }
}

// ---------------------------------------------------------------------------
// Attention: one block (256 threads) per tile of TQ=16 prot rows (same batch).
// K staged into smem in 32-key chunks; each warp owns 2 Q rows via half-warps.
// Attn matrix was pre-zeroed, so only the segment columns are written here.
// ---------------------------------------------------------------------------
__global__ __launch_bounds__(256) void attn_kernel(
    float* __restrict__ out, float* __restrict__ attn)
{
    const int t = blockIdx.x;
    if (t >= g_ntiles) return;

    const int row0 = g_trow[t];
    const int nr   = g_tn[t];
    const int b    = g_tb[t];
    const int s    = g_ss[b];
    int m = g_se[b] - s;
    if (m > MSEG) m = MSEG;          // unreachable; memory safety
    const int e_eff = s + m;

    __shared__ __align__(16) float sc[TQ * MSEG];        // 32 KB
    __shared__ __align__(16) float Ks[CKEYS * HIDDEN];   // 32 KB

    const int tid  = threadIdx.x;
    const int warp = tid >> 5;
    const int lane = tid & 31;

    if (m > 0) {
        const int h  = lane >> 4;
        const int hl = lane & 15;
        const int rr = warp * 2 + h;
        const int qr = row0 + ((rr < nr) ? rr : nr - 1);

        const float4* Q4 = (const float4*)g_Q + (size_t)qr * 64;
        const float4 q0 = Q4[hl];
        const float4 q1 = Q4[hl + 16];
        const float4 q2 = Q4[hl + 32];
        const float4 q3 = Q4[hl + 48];

        float4* Ks4 = (float4*)Ks;

        for (int c0 = 0; c0 < m; c0 += CKEYS) {
            const int cn = (m - c0 < CKEYS) ? (m - c0) : CKEYS;
            __syncthreads();
            const float4* Kg = (const float4*)g_K + (size_t)(s + c0) * 64;
            for (int idx = tid; idx < cn * 64; idx += 256)
                Ks4[idx] = Kg[idx];
            __syncthreads();

            for (int j = 0; j < cn; j++) {
                const float4* Kr = Ks4 + j * 64;
                const float4 k0 = Kr[hl];
                const float4 k1 = Kr[hl + 16];
                const float4 k2 = Kr[hl + 32];
                const float4 k3 = Kr[hl + 48];
                float d = q0.x*k0.x + q0.y*k0.y + q0.z*k0.z + q0.w*k0.w
                        + q1.x*k1.x + q1.y*k1.y + q1.z*k1.z + q1.w*k1.w
                        + q2.x*k2.x + q2.y*k2.y + q2.z*k2.z + q2.w*k2.w
                        + q3.x*k3.x + q3.y*k3.y + q3.z*k3.z + q3.w*k3.w;
                #pragma unroll
                for (int off = 8; off; off >>= 1)
                    d += __shfl_xor_sync(0xffffffffu, d, off);
                if (hl == 0) sc[rr * MSEG + c0 + j] = d * 0.0625f;  // 1/sqrt(256)
            }
        }
        __syncthreads();

        // Softmax: warp w normalizes rows 2w, 2w+1.
        #pragma unroll
        for (int rr2 = 0; rr2 < 2; rr2++) {
            float* row = sc + (warp * 2 + rr2) * MSEG;
            float mx = -INFINITY;
            for (int j = lane; j < m; j += 32) mx = fmaxf(mx, row[j]);
            #pragma unroll
            for (int off = 16; off; off >>= 1)
                mx = fmaxf(mx, __shfl_xor_sync(0xffffffffu, mx, off));
            float sum = 0.f;
            for (int j = lane; j < m; j += 32) {
                const float v = __expf(row[j] - mx);
                row[j] = v;
                sum += v;
            }
            #pragma unroll
            for (int off = 16; off; off >>= 1)
                sum += __shfl_xor_sync(0xffffffffu, sum, off);
            const float inv = 1.f / sum;
            for (int j = lane; j < m; j += 32) row[j] *= inv;
        }
        __syncthreads();
    }

    // Segment-only attn write (matrix pre-zeroed by proj_zero_kernel).
    for (int r = 0; r < nr; r++) {
        float* arow = attn + (size_t)(row0 + r) * N_MOL;
        const float* row = sc + r * MSEG;
        for (int c = s + tid; c < e_eff; c += 256)
            arow[c] = row[c - s];
    }

    // out[row0+r][tid] = sum_j p[r][j] * V[s+j][tid]; 16 register accumulators.
    float acc[TQ];
    #pragma unroll
    for (int r = 0; r < TQ; r++) acc[r] = 0.f;

    int j = 0;
    for (; j + 3 < m; j += 4) {
        const float v0 = g_V[(size_t)(s + j + 0) * HIDDEN + tid];
        const float v1 = g_V[(size_t)(s + j + 1) * HIDDEN + tid];
        const float v2 = g_V[(size_t)(s + j + 2) * HIDDEN + tid];
        const float v3 = g_V[(size_t)(s + j + 3) * HIDDEN + tid];
        #pragma unroll
        for (int r = 0; r < TQ; r++) {
            const float4 p = *(const float4*)&sc[r * MSEG + j];
            float a = acc[r];
            a = fmaf(p.x, v0, a);
            a = fmaf(p.y, v1, a);
            a = fmaf(p.z, v2, a);
            a = fmaf(p.w, v3, a);
            acc[r] = a;
        }
    }
    for (; j < m; j++) {
        const float v0 = g_V[(size_t)(s + j) * HIDDEN + tid];
        #pragma unroll
        for (int r = 0; r < TQ; r++)
            acc[r] = fmaf(sc[r * MSEG + j], v0, acc[r]);
    }

    #pragma unroll
    for (int r = 0; r < TQ; r++)
        if (r < nr) out[(size_t)(row0 + r) * HIDDEN + tid] = acc[r];
}

// ---------------------------------------------------------------------------
extern "C" void kernel_launch(void* const* d_in, const int* in_sizes, int n_in,
                              void* d_out, int out_size)
{
    const float* prot_embed = (const float*)d_in[0];
    const float* mol_embed  = (const float*)d_in[1];
    const int*   prot_batch = (const int*)d_in[2];
    const int*   mol_batch  = (const int*)d_in[3];
    const float* Wq = (const float*)d_in[4];
    const float* bq = (const float*)d_in[5];
    const float* Wk = (const float*)d_in[6];
    const float* bk = (const float*)d_in[7];
    const float* Wv = (const float*)d_in[8];
    const float* bv = (const float*)d_in[9];

    float* out  = (float*)d_out;                              // [N_PROT, HIDDEN]
    float* attn = (float*)d_out + (size_t)N_PROT * HIDDEN;    // [N_PROT, N_MOL]

    bounds_kernel<<<(N_PROT + 255) / 256, 256>>>(prot_batch, mol_batch);
    tiles_kernel<<<1, 32>>>();
    proj_zero_kernel<<<NPROJ + NZERO, 256>>>(prot_embed, mol_embed,
                                             Wq, bq, Wk, bk, Wv, bv, attn);
    attn_kernel<<<MAXTILES, 256>>>(out, attn);
}